// round 15
// baseline (speedup 1.0000x reference)
#include <cuda_runtime.h>
#include <cuda_bf16.h>
#include <stdint.h>

// Embedding_44994077393181
// out[b,t,:] = W_emb_tok[ argnz(X[b,t,:]) , : ] + X_emb_pos[t,:]
// X: (2,2048,32000) fp32 one-hot; W: (32000,1024) fp32; pos: (2048,1024) fp32
//
// Converged engine at the modeled chunk-size optimum:
//   BW(S) = 6.4 TB/s * S/(S+0.86KB)  (fit across R1/R3/R13);
//   bytes(S) = 303 MB + 2048*S; t(S) minimized near S ~= 11.4 KB.
// -> 96-thread CTA (3 warps) per row, 3072-float (12 KB) chunks, 8 unguarded
//    constant-offset uint4 loads/thread/pass (pointer bump; 10 full passes
//    cover f4 [0,7680), guarded tail covers [7680,8000)), integer-OR nonzero
//    detect (one-hot bits 0x0/0x3F800000), in-register index recovery,
//    __ldcs X stream, __stcs output stream. Fused gather + positional add.

#define VOCAB    32000
#define EMB_DIM  1024
#define CTX      2048
#define NROWS    4096         // BATCH * CTX
#define THREADS  96
#define CHUNKF4  768          // float4 per pass = 96 threads * 8  (3072 floats)
#define NFULL    10           // unguarded full passes: 10*768 = 7680 f4
#define NQ       8000         // float4 per row

__global__ __launch_bounds__(THREADS)
void embed_onehot_kernel(const float* __restrict__ X,
                         const float* __restrict__ W,
                         const float* __restrict__ pos,
                         float* __restrict__ out)
{
    const int row = blockIdx.x;            // 0..4095  (b = row / CTX, t = row % CTX)
    const int t   = row & (CTX - 1);
    const int tid = threadIdx.x;

    // Per-thread base pointer: advance by CHUNKF4 each pass; loads then use
    // constant offsets j*THREADS (folded into the LDG immediate).
    const uint4* xp = reinterpret_cast<const uint4*>(X + (size_t)row * VOCAB) + tid;

    __shared__ int s_idx;

    int pass = 0;

    #pragma unroll 1
    for (; pass < NFULL; ++pass) {
        // 8 unguarded, constant-offset 16B loads (12 KB per CTA in flight).
        uint4 v[8];
        #pragma unroll
        for (int j = 0; j < 8; ++j)
            v[j] = __ldcs(xp + j * THREADS);

        // Cheap detect: OR-reduce raw bits (one-hot: 0x0 / 0x3F800000).
        uint32_t acc = 0u;
        #pragma unroll
        for (int j = 0; j < 8; ++j)
            acc |= (v[j].x | v[j].y) | (v[j].z | v[j].w);

        // Rare path (once per row): pinpoint element from live registers.
        int found = -1;
        if (acc != 0u) {
            const int base_i = (pass * CHUNKF4 + tid) << 2;
            #pragma unroll
            for (int j = 0; j < 8; ++j) {
                const int i = base_i + (j * THREADS << 2);
                if (v[j].x) found = i;
                if (v[j].y) found = i + 1;
                if (v[j].z) found = i + 2;
                if (v[j].w) found = i + 3;
            }
            s_idx = found;                 // exactly one nonzero per row
        }

        if (__syncthreads_or(found >= 0)) break;
        xp += CHUNKF4;
    }

    // Final partial pass: f4 slots [7680, 8000), guarded.
    // Only threads with p < NQ participate (p = 7680 + j*96 + tid).
    if (pass == NFULL) {
        int found = -1;
        #pragma unroll
        for (int j = 0; j < 4; ++j) {      // 4*96 = 384 >= 320 remaining f4
            const int p = NFULL * CHUNKF4 + j * THREADS + tid;
            if (p < NQ) {
                const uint4 v = __ldcs(xp + j * THREADS);
                if (v.x | v.y | v.z | v.w) {
                    const int i = p << 2;
                    if (v.x) found = i;
                    if (v.y) found = i + 1;
                    if (v.z) found = i + 2;
                    if (v.w) found = i + 3;
                }
            }
        }
        if (found >= 0) s_idx = found;
    }

    __syncthreads();                       // s_idx visible on all exit paths
    const int idx = s_idx;

    // Fused gather + positional add: 1024 floats = 256 f4; 96 threads cover
    // slots tid, tid+96, tid+192 (guarded: 3*96 = 288 > 256).
    const float4* wrow = reinterpret_cast<const float4*>(W   + (size_t)idx * EMB_DIM);
    const float4* prow = reinterpret_cast<const float4*>(pos + (size_t)t   * EMB_DIM);
    float4*       orow = reinterpret_cast<float4*>(out + (size_t)row * EMB_DIM);

    #pragma unroll
    for (int j = 0; j < 3; ++j) {
        const int c = j * THREADS + tid;
        if (c < EMB_DIM / 4) {
            const float4 wv = __ldg(wrow + c);
            const float4 pv = __ldg(prow + c);
            float4 o;
            o.x = wv.x + pv.x;
            o.y = wv.y + pv.y;
            o.z = wv.z + pv.z;
            o.w = wv.w + pv.w;
            __stcs(orow + c, o);
        }
    }
}

extern "C" void kernel_launch(void* const* d_in, const int* in_sizes, int n_in,
                              void* d_out, int out_size)
{
    const float* X   = (const float*)d_in[0];   // (2,2048,32000)
    const float* W   = (const float*)d_in[1];   // (32000,1024)
    const float* pos = (const float*)d_in[2];   // (2048,1024)
    float* out = (float*)d_out;                 // (2,2048,1024)

    embed_onehot_kernel<<<NROWS, THREADS>>>(X, W, pos, out);
}

// round 17
// speedup vs baseline: 1.0368x; 1.0368x over previous
#include <cuda_runtime.h>
#include <cuda_bf16.h>
#include <stdint.h>

// Embedding_44994077393181  — FINAL (converged, best = R14, 51.26 us)
// out[b,t,:] = W_emb_tok[ argnz(X[b,t,:]) , : ] + X_emb_pos[t,:]
// X: (2,2048,32000) fp32 one-hot; W: (32000,1024) fp32; pos: (2048,1024) fp32
//
// Converged engine:
//   - 64-thread CTA (2 warps) per row; lock-step early-exit scan in
//     2048-float (8 KB) chunks — measured optimum of the bytes-vs-BW trade
//     (BW(S) saturates at ~5.8-6.0 TB/s by S=8KB; larger chunks only add bytes)
//   - 8 unguarded constant-offset uint4 loads/thread/pass (pointer bump;
//     passes 0..14 cover f4 [0,7680) with no bounds checks), guarded tail
//   - integer-OR nonzero detect (one-hot bits: 0x0 / 0x3F800000) — ~70%
//     cheaper than FP compares; in-register index recovery on the rare path
//   - X streamed __ldcs (evict-first), W/pos via __ldg, out via __stcs so the
//     17 MB write stream doesn't evict W duplicates / pos second-reads from L2
//   - fused gather + positional add (64 threads * 4 float4)
// (Resubmission: this source passed R14 at 51.26 us; R16 bench attempt died
// to container infra before reaching the GPU.)

#define VOCAB    32000
#define EMB_DIM  1024
#define CTX      2048
#define NROWS    4096         // BATCH * CTX
#define THREADS  64
#define CHUNKF4  512          // float4 per pass = 64 threads * 8  (2048 floats)
#define NFULL    15           // unguarded full passes: 15*512 = 7680 f4
#define NQ       8000         // float4 per row

__global__ __launch_bounds__(THREADS)
void embed_onehot_kernel(const float* __restrict__ X,
                         const float* __restrict__ W,
                         const float* __restrict__ pos,
                         float* __restrict__ out)
{
    const int row = blockIdx.x;            // 0..4095  (b = row / CTX, t = row % CTX)
    const int t   = row & (CTX - 1);
    const int tid = threadIdx.x;

    // Per-thread base pointer: advance by CHUNKF4 each pass; loads then use
    // constant offsets j*THREADS (folded into the LDG immediate).
    const uint4* xp = reinterpret_cast<const uint4*>(X + (size_t)row * VOCAB) + tid;

    __shared__ int s_idx;

    int pass = 0;

    #pragma unroll 1
    for (; pass < NFULL; ++pass) {
        // 8 unguarded, constant-offset 16B loads (8 KB per CTA in flight).
        uint4 v[8];
        #pragma unroll
        for (int j = 0; j < 8; ++j)
            v[j] = __ldcs(xp + j * THREADS);

        // Cheap detect: OR-reduce raw bits (one-hot: 0x0 / 0x3F800000).
        uint32_t acc = 0u;
        #pragma unroll
        for (int j = 0; j < 8; ++j)
            acc |= (v[j].x | v[j].y) | (v[j].z | v[j].w);

        // Rare path (once per row): pinpoint element from live registers.
        int found = -1;
        if (acc != 0u) {
            const int base_i = (pass * CHUNKF4 + tid) << 2;
            #pragma unroll
            for (int j = 0; j < 8; ++j) {
                const int i = base_i + (j * THREADS << 2);
                if (v[j].x) found = i;
                if (v[j].y) found = i + 1;
                if (v[j].z) found = i + 2;
                if (v[j].w) found = i + 3;
            }
            s_idx = found;                 // exactly one nonzero per row
        }

        if (__syncthreads_or(found >= 0)) break;
        xp += CHUNKF4;
    }

    // Final partial pass: f4 slots [7680, 8000), guarded.
    if (pass == NFULL) {
        int found = -1;
        #pragma unroll
        for (int j = 0; j < 8; ++j) {
            const int p = NFULL * CHUNKF4 + j * THREADS + tid;
            if (p < NQ) {
                const uint4 v = __ldcs(xp + j * THREADS);
                if (v.x | v.y | v.z | v.w) {
                    const int i = p << 2;
                    if (v.x) found = i;
                    if (v.y) found = i + 1;
                    if (v.z) found = i + 2;
                    if (v.w) found = i + 3;
                }
            }
        }
        if (found >= 0) s_idx = found;
    }

    __syncthreads();                       // s_idx visible on all exit paths
    const int idx = s_idx;

    // Fused gather + positional add: 1024 floats = 64 threads * 4 float4.
    // Output stored evict-first so the write stream doesn't pollute L2.
    const float4* wrow = reinterpret_cast<const float4*>(W   + (size_t)idx * EMB_DIM);
    const float4* prow = reinterpret_cast<const float4*>(pos + (size_t)t   * EMB_DIM);
    float4*       orow = reinterpret_cast<float4*>(out + (size_t)row * EMB_DIM);

    #pragma unroll
    for (int j = 0; j < 4; ++j) {
        const int c = j * THREADS + tid;
        const float4 wv = __ldg(wrow + c);
        const float4 pv = __ldg(prow + c);
        float4 o;
        o.x = wv.x + pv.x;
        o.y = wv.y + pv.y;
        o.z = wv.z + pv.z;
        o.w = wv.w + pv.w;
        __stcs(orow + c, o);
    }
}

extern "C" void kernel_launch(void* const* d_in, const int* in_sizes, int n_in,
                              void* d_out, int out_size)
{
    const float* X   = (const float*)d_in[0];   // (2,2048,32000)
    const float* W   = (const float*)d_in[1];   // (32000,1024)
    const float* pos = (const float*)d_in[2];   // (2048,1024)
    float* out = (float*)d_out;                 // (2,2048,1024)

    embed_onehot_kernel<<<NROWS, THREADS>>>(X, W, pos, out);
}